// round 3
// baseline (speedup 1.0000x reference)
#include <cuda_runtime.h>
#include <math.h>

// Problem shapes (fixed by the dataset)
constexpr int D   = 272;          // capsule feature dim
constexpr int NC  = 19;           // num classes
constexpr int D4  = D / 4;        // 68 float4 per row
constexpr int NTH = 288;          // 9 warps; 272 active in accumulation
constexpr int GROUPS = 4;         // points processed in parallel per iteration
constexpr int CHUNK  = 512;       // indices staged in shared per pass
constexpr int MAX_NI = 8192;

// Scratch: segment start offsets. seg_start[s] = first p with segment_ids[p] >= s.
__device__ int g_seg_start[MAX_NI + 1];

// ---------------------------------------------------------------------------
// Kernel 1: compute segment boundaries from sorted segment_ids.
// Every s in [0, NI] is written exactly once (deterministic, no init needed).
// ---------------------------------------------------------------------------
__global__ void seg_bounds_kernel(const int* __restrict__ seg, int P, int NI) {
    int p = blockIdx.x * blockDim.x + threadIdx.x;
    if (p >= P) return;
    int cur  = min(seg[p], NI - 1);
    int prev = (p == 0) ? -1 : min(seg[p - 1], NI - 1);
    for (int s = prev + 1; s <= cur; ++s) g_seg_start[s] = p;
    if (p == P - 1) {
        for (int s = cur + 1; s <= NI; ++s) g_seg_start[s] = P;
    }
}

// ---------------------------------------------------------------------------
// Kernel 2: one CTA per segment. Gather+accumulate rows (float4, 4 points in
// flight per iteration), mean-pool, then fused 272x19 GEMV + sigmoid.
// ---------------------------------------------------------------------------
__global__ __launch_bounds__(NTH, 4)
void capsule_segment_kernel(const float*  __restrict__ feats,      // [B*H*W, D]
                            const float*  __restrict__ Wmat,       // [D, NC]
                            const float*  __restrict__ bias,       // [NC]
                            const int*    __restrict__ point_idx,  // [P]
                            float*        __restrict__ out)        // [NI, NC]
{
    __shared__ int   s_idx[CHUNK];
    __shared__ float s_red[GROUPS][D];   // per-group partial sums; row 0 reused as pooled

    const int seg   = blockIdx.x;
    const int tid   = threadIdx.x;
    const int start = g_seg_start[seg];
    const int end   = g_seg_start[seg + 1];
    const int count = end - start;

    const int g  = tid / D4;     // point group 0..3 (valid for tid < 272)
    const int c4 = tid % D4;     // float4 column 0..67
    const bool active = (tid < GROUPS * D4);

    float4 acc = make_float4(0.f, 0.f, 0.f, 0.f);
    const float4* feats4 = reinterpret_cast<const float4*>(feats);

    for (int base = start; base < end; base += CHUNK) {
        const int n = min(CHUNK, end - base);
        for (int i = tid; i < n; i += NTH) s_idx[i] = point_idx[base + i];
        __syncthreads();
        if (active) {
            #pragma unroll 4
            for (int i = g; i < n; i += GROUPS) {
                const int idx = s_idx[i];
                const float4 v = __ldg(feats4 + (size_t)idx * D4 + c4);
                acc.x += v.x; acc.y += v.y; acc.z += v.z; acc.w += v.w;
            }
        }
        __syncthreads();
    }

    // Spill per-thread accumulators to shared for cross-group reduction.
    if (active) {
        s_red[g][4 * c4 + 0] = acc.x;
        s_red[g][4 * c4 + 1] = acc.y;
        s_red[g][4 * c4 + 2] = acc.z;
        s_red[g][4 * c4 + 3] = acc.w;
    }
    __syncthreads();

    // pooled[d] = (sum over groups) / max(count, 1); store into s_red[0][d].
    const float inv_cnt = 1.0f / (float)max(count, 1);
    if (tid < D) {
        float s = s_red[0][tid] + s_red[1][tid] + s_red[2][tid] + s_red[3][tid];
        s_red[0][tid] = s * inv_cnt;
    }
    __syncthreads();

    // Fused linear + sigmoid: 9 warps cover 19 classes; shuffle-reduce over D.
    const int warp = tid >> 5;
    const int lane = tid & 31;
    for (int c = warp; c < NC; c += NTH / 32) {
        float s = 0.f;
        #pragma unroll
        for (int d = lane; d < D; d += 32)
            s += s_red[0][d] * __ldg(&Wmat[d * NC + c]);
        #pragma unroll
        for (int off = 16; off > 0; off >>= 1)
            s += __shfl_down_sync(0xffffffffu, s, off);
        if (lane == 0) {
            float z = s + __ldg(&bias[c]);
            out[seg * NC + c] = 1.0f / (1.0f + expf(-z));
        }
    }
}

// ---------------------------------------------------------------------------
// Launch
// ---------------------------------------------------------------------------
extern "C" void kernel_launch(void* const* d_in, const int* in_sizes, int n_in,
                              void* d_out, int out_size) {
    const float* feats     = (const float*)d_in[0];   // class_capsules [B,H,W,D]
    const float* Wmat      = (const float*)d_in[1];   // [D, NC]
    const float* bias      = (const float*)d_in[2];   // [NC]
    const int*   point_idx = (const int*)  d_in[3];   // [P]
    const int*   seg_ids   = (const int*)  d_in[4];   // [P] (sorted)
    float*       out       = (float*)d_out;           // [NI, NC]

    const int P  = in_sizes[3];
    int NI = out_size / NC;                           // 4096 expected
    if (NI > MAX_NI) NI = MAX_NI;                     // protect g_seg_start bounds

    seg_bounds_kernel<<<(P + 255) / 256, 256>>>(seg_ids, P, NI);
    capsule_segment_kernel<<<NI, NTH>>>(feats, Wmat, bias, point_idx, out);
}